// round 3
// baseline (speedup 1.0000x reference)
#include <cuda_runtime.h>

#define B_   64
#define LQ_  1024
#define LK_  1024
#define D_   128
#define INV_T 0.08838834764831845f   // 1/sqrt(128)

// ---------------------------------------------------------------------------
// f32x2 packed helpers (Blackwell fp32x2 path; ptxas won't auto-fuse from C++)
// ---------------------------------------------------------------------------
__device__ __forceinline__ unsigned long long pack2(float x, float y) {
    unsigned long long r;
    asm("mov.b64 %0, {%1, %2};" : "=l"(r) : "f"(x), "f"(y));
    return r;
}
__device__ __forceinline__ void unpack2(unsigned long long v, float& x, float& y) {
    asm("mov.b64 {%0, %1}, %2;" : "=f"(x), "=f"(y) : "l"(v));
}
__device__ __forceinline__ void ffma2(unsigned long long& c, unsigned long long a, unsigned long long b) {
    asm("fma.rn.f32x2 %0, %1, %2, %3;" : "=l"(c) : "l"(a), "l"(b), "l"(c));
}

// ---------------------------------------------------------------------------
// Kernel 1: S[b, q, k] = dot(Q[b,q,:], K[b,k,:]) * INV_T
// Writes raw scores into the log_attn output region (finalized by kernel 2).
// ---------------------------------------------------------------------------
__global__ __launch_bounds__(256) void scores_kernel(
    const float* __restrict__ Q, const float* __restrict__ Km, float* __restrict__ S)
{
    __shared__ float Qs[32][132];
    __shared__ float Ks[32][132];

    const int b  = blockIdx.z;
    const int qt = blockIdx.y;
    const int kt = blockIdx.x;
    const int t  = threadIdx.x;
    const int tx = t & 15;
    const int ty = t >> 4;

    const float* Qb = Q  + ((size_t)b * LQ_ + (size_t)qt * 128) * D_;
    const float* Kb = Km + ((size_t)b * LK_ + (size_t)kt * 128) * D_;

    unsigned long long acc[8][4];
    #pragma unroll
    for (int i = 0; i < 8; i++)
        #pragma unroll
        for (int j = 0; j < 4; j++) acc[i][j] = 0ULL;

    const int lc = (t & 7) * 4;
    const int lr = t >> 3;

    for (int dc = 0; dc < 4; dc++) {
        #pragma unroll
        for (int i = 0; i < 4; i++) {
            int r = lr + 32 * i;
            float4 qv = *(const float4*)(Qb + (size_t)r * D_ + dc * 32 + lc);
            Qs[lc + 0][r] = qv.x; Qs[lc + 1][r] = qv.y;
            Qs[lc + 2][r] = qv.z; Qs[lc + 3][r] = qv.w;
            float4 kv = *(const float4*)(Kb + (size_t)r * D_ + dc * 32 + lc);
            Ks[lc + 0][r] = kv.x; Ks[lc + 1][r] = kv.y;
            Ks[lc + 2][r] = kv.z; Ks[lc + 3][r] = kv.w;
        }
        __syncthreads();

        #pragma unroll
        for (int kk = 0; kk < 32; kk++) {
            float4 a0 = *(const float4*)&Qs[kk][ty * 8];
            float4 a1 = *(const float4*)&Qs[kk][ty * 8 + 4];
            float4 b0 = *(const float4*)&Ks[kk][tx * 8];
            float4 b1 = *(const float4*)&Ks[kk][tx * 8 + 4];
            unsigned long long bp[4];
            bp[0] = pack2(b0.x, b0.y); bp[1] = pack2(b0.z, b0.w);
            bp[2] = pack2(b1.x, b1.y); bp[3] = pack2(b1.z, b1.w);
            float av[8] = {a0.x, a0.y, a0.z, a0.w, a1.x, a1.y, a1.z, a1.w};
            #pragma unroll
            for (int i = 0; i < 8; i++) {
                unsigned long long ap = pack2(av[i], av[i]);
                #pragma unroll
                for (int j = 0; j < 4; j++) ffma2(acc[i][j], ap, bp[j]);
            }
        }
        __syncthreads();
    }

    float* Sb = S + ((size_t)b * LQ_ + (size_t)qt * 128) * LK_ + (size_t)kt * 128;
    #pragma unroll
    for (int i = 0; i < 8; i++) {
        int r = ty * 8 + i;
        float o[8];
        #pragma unroll
        for (int j = 0; j < 4; j++) unpack2(acc[i][j], o[2 * j], o[2 * j + 1]);
        float4 w0 = make_float4(o[0] * INV_T, o[1] * INV_T, o[2] * INV_T, o[3] * INV_T);
        float4 w1 = make_float4(o[4] * INV_T, o[5] * INV_T, o[6] * INV_T, o[7] * INV_T);
        *(float4*)(Sb + (size_t)r * LK_ + tx * 8)     = w0;
        *(float4*)(Sb + (size_t)r * LK_ + tx * 8 + 4) = w1;
    }
}

// ---------------------------------------------------------------------------
// Kernel 2: per-row double softmax.
// MASK IS INT32 (bool inputs are materialized as int32 by the harness).
// Writes attn = softmax(masked scores) and rewrites S in-place with
// log_softmax of the UNMASKED scores.
// ---------------------------------------------------------------------------
__global__ __launch_bounds__(256) void softmax_kernel(
    float* __restrict__ S, float* __restrict__ A, const int* __restrict__ M)
{
    __shared__ float2 red[8];
    const int t = threadIdx.x;
    const size_t row = blockIdx.x;

    float4 sv = ((const float4*)(S + row * LK_))[t];
    int4  mv = ((const int4*)(M + row * LK_))[t];

    float mU = fmaxf(fmaxf(sv.x, sv.y), fmaxf(sv.z, sv.w));
    float mM = -3.0e38f;
    if (!mv.x) mM = sv.x;
    if (!mv.y) mM = fmaxf(mM, sv.y);
    if (!mv.z) mM = fmaxf(mM, sv.z);
    if (!mv.w) mM = fmaxf(mM, sv.w);

    #pragma unroll
    for (int o = 16; o > 0; o >>= 1) {
        mU = fmaxf(mU, __shfl_xor_sync(0xffffffffu, mU, o));
        mM = fmaxf(mM, __shfl_xor_sync(0xffffffffu, mM, o));
    }
    if ((t & 31) == 0) red[t >> 5] = make_float2(mU, mM);
    __syncthreads();
    #pragma unroll
    for (int w = 0; w < 8; w++) { mU = fmaxf(mU, red[w].x); mM = fmaxf(mM, red[w].y); }
    __syncthreads();

    float e0 = __expf(sv.x - mU), e1 = __expf(sv.y - mU),
          e2 = __expf(sv.z - mU), e3 = __expf(sv.w - mU);
    float sumU = (e0 + e1) + (e2 + e3);
    float f0 = mv.x ? 0.f : __expf(sv.x - mM);
    float f1 = mv.y ? 0.f : __expf(sv.y - mM);
    float f2 = mv.z ? 0.f : __expf(sv.z - mM);
    float f3 = mv.w ? 0.f : __expf(sv.w - mM);
    float sumM = (f0 + f1) + (f2 + f3);

    #pragma unroll
    for (int o = 16; o > 0; o >>= 1) {
        sumU += __shfl_xor_sync(0xffffffffu, sumU, o);
        sumM += __shfl_xor_sync(0xffffffffu, sumM, o);
    }
    if ((t & 31) == 0) red[t >> 5] = make_float2(sumU, sumM);
    __syncthreads();
    float sU = 0.f, sM = 0.f;
    #pragma unroll
    for (int w = 0; w < 8; w++) { sU += red[w].x; sM += red[w].y; }

    const float lse = mU + __logf(sU);
    const float inv = 1.0f / sM;

    ((float4*)(A + row * LK_))[t] = make_float4(f0 * inv, f1 * inv, f2 * inv, f3 * inv);
    ((float4*)(S + row * LK_))[t] =
        make_float4(sv.x - lse, sv.y - lse, sv.z - lse, sv.w - lse);
}

// ---------------------------------------------------------------------------
// Kernel 3: O[b, q, d] = sum_k A[b,q,k] * V[b,k,d]
// ---------------------------------------------------------------------------
__global__ __launch_bounds__(256) void out_kernel(
    const float* __restrict__ A, const float* __restrict__ V, float* __restrict__ O)
{
    __shared__ float As[32][132];
    __shared__ float Vs[32][132];

    const int b  = blockIdx.y;
    const int qt = blockIdx.x;
    const int t  = threadIdx.x;
    const int tx = t & 15;
    const int ty = t >> 4;

    const float* Ab = A + ((size_t)b * LQ_ + (size_t)qt * 128) * LK_;
    const float* Vb = V + (size_t)b * LK_ * D_;

    unsigned long long acc[8][4];
    #pragma unroll
    for (int i = 0; i < 8; i++)
        #pragma unroll
        for (int j = 0; j < 4; j++) acc[i][j] = 0ULL;

    const int lc = (t & 7) * 4;
    const int lr = t >> 3;
    const int vr = t >> 5;
    const int vc = (t & 31) * 4;

    for (int kc = 0; kc < 32; kc++) {
        #pragma unroll
        for (int i = 0; i < 4; i++) {
            int r = lr + 32 * i;
            float4 av = *(const float4*)(Ab + (size_t)r * LK_ + kc * 32 + lc);
            As[lc + 0][r] = av.x; As[lc + 1][r] = av.y;
            As[lc + 2][r] = av.z; As[lc + 3][r] = av.w;
            int vrow = vr + 8 * i;
            float4 vv = *(const float4*)(Vb + (size_t)(kc * 32 + vrow) * D_ + vc);
            *(float4*)&Vs[vrow][vc] = vv;
        }
        __syncthreads();

        #pragma unroll
        for (int kk = 0; kk < 32; kk++) {
            float4 a0 = *(const float4*)&As[kk][ty * 8];
            float4 a1 = *(const float4*)&As[kk][ty * 8 + 4];
            float4 b0 = *(const float4*)&Vs[kk][tx * 8];
            float4 b1 = *(const float4*)&Vs[kk][tx * 8 + 4];
            unsigned long long bp[4];
            bp[0] = pack2(b0.x, b0.y); bp[1] = pack2(b0.z, b0.w);
            bp[2] = pack2(b1.x, b1.y); bp[3] = pack2(b1.z, b1.w);
            float av[8] = {a0.x, a0.y, a0.z, a0.w, a1.x, a1.y, a1.z, a1.w};
            #pragma unroll
            for (int i = 0; i < 8; i++) {
                unsigned long long ap = pack2(av[i], av[i]);
                #pragma unroll
                for (int j = 0; j < 4; j++) ffma2(acc[i][j], ap, bp[j]);
            }
        }
        __syncthreads();
    }

    float* Ob = O + ((size_t)b * LQ_ + (size_t)qt * 128) * D_;
    #pragma unroll
    for (int i = 0; i < 8; i++) {
        int r = ty * 8 + i;
        float o[8];
        #pragma unroll
        for (int j = 0; j < 4; j++) unpack2(acc[i][j], o[2 * j], o[2 * j + 1]);
        *(float4*)(Ob + (size_t)r * D_ + tx * 8)     = make_float4(o[0], o[1], o[2], o[3]);
        *(float4*)(Ob + (size_t)r * D_ + tx * 8 + 4) = make_float4(o[4], o[5], o[6], o[7]);
    }
}

// ---------------------------------------------------------------------------
// Launch: inputs (metadata order): q, k, v, attn_mask (int32).
// d_out layout (tuple concatenated): output | attn | log_attn.
// Raw scores are staged in the log_attn region (overwritten in-place).
// ---------------------------------------------------------------------------
extern "C" void kernel_launch(void* const* d_in, const int* in_sizes, int n_in,
                              void* d_out, int out_size)
{
    (void)in_sizes; (void)n_in; (void)out_size;
    const float* Q = (const float*)d_in[0];
    const float* K = (const float*)d_in[1];
    const float* V = (const float*)d_in[2];
    const int*   M = (const int*)d_in[3];

    float* O   = (float*)d_out;
    float* ATT = O   + (size_t)B_ * LQ_ * D_;
    float* LA  = ATT + (size_t)B_ * LQ_ * LK_;

    scores_kernel<<<dim3(LK_ / 128, LQ_ / 128, B_), 256>>>(Q, K, LA);
    softmax_kernel<<<B_ * LQ_, 256>>>(LA, ATT, M);
    out_kernel<<<dim3(LQ_ / 128, B_), 256>>>(ATT, V, O);
}

// round 5
// speedup vs baseline: 1.3851x; 1.3851x over previous
#include <cuda_runtime.h>
#include <cuda_bf16.h>
#include <cstdint>

#define B_   64
#define LQ_  1024
#define LK_  1024
#define D_   128
#define INV_T 0.08838834764831845f   // 1/sqrt(128)

// V transposed to [b][d][k], bf16 hi/lo split (16 MB each).
__device__ __nv_bfloat16 g_Vt_hi[(size_t)B_ * D_ * LK_];
__device__ __nv_bfloat16 g_Vt_lo[(size_t)B_ * D_ * LK_];

// ---------------------------------------------------------------------------
// helpers
// ---------------------------------------------------------------------------
__device__ __forceinline__ uint32_t smem_u32(const void* p) {
    uint32_t a;
    asm("{ .reg .u64 t; cvta.to.shared.u64 t, %1; cvt.u32.u64 %0, t; }" : "=r"(a) : "l"(p));
    return a;
}
__device__ __forceinline__ void ldsm_x4(uint32_t addr, uint32_t* r) {
    asm volatile("ldmatrix.sync.aligned.m8n8.x4.shared.b16 {%0,%1,%2,%3}, [%4];"
                 : "=r"(r[0]), "=r"(r[1]), "=r"(r[2]), "=r"(r[3]) : "r"(addr));
}
__device__ __forceinline__ void mma16816(float* d, const uint32_t* a, const uint32_t* b) {
    asm volatile("mma.sync.aligned.m16n8k16.row.col.f32.bf16.bf16.f32 "
                 "{%0,%1,%2,%3}, {%4,%5,%6,%7}, {%8,%9}, {%0,%1,%2,%3};"
                 : "+f"(d[0]), "+f"(d[1]), "+f"(d[2]), "+f"(d[3])
                 : "r"(a[0]), "r"(a[1]), "r"(a[2]), "r"(a[3]), "r"(b[0]), "r"(b[1]));
}
__device__ __forceinline__ uint32_t pk_bf2(__nv_bfloat16 a, __nv_bfloat16 b) {
    __nv_bfloat162 t(a, b);
    return *reinterpret_cast<uint32_t*>(&t);
}
__device__ __forceinline__ void split_f(float x, __nv_bfloat16& h, __nv_bfloat16& l) {
    h = __float2bfloat16(x);
    l = __float2bfloat16(x - __bfloat162float(h));
}

// smem: 4 tiles of [128 rows][64 bf16 = 128B] = 16KB each
#define T_AHI 0
#define T_ALO 16384
#define T_BHI 32768
#define T_BLO 49152
#define SM_TOTAL 65536

// ---------------------------------------------------------------------------
// GEMM core: C[128x128] += 3-term split MMA over one 64-wide K chunk.
// Warp grid 2(m) x 4(n); warp tile 64x32. acc[mt][nt][4].
// ---------------------------------------------------------------------------
__device__ __forceinline__ void mma_chunk(uint32_t sb, int lane, int wm, int wn,
                                          float acc[4][4][4])
{
    const uint32_t aRow  = (uint32_t)(wm * 64 + (lane & 15)) * 128u;
    const uint32_t aXor  = (uint32_t)(lane & 7) << 4;
    const uint32_t aCol0 = (uint32_t)(lane >> 4) << 4;
    const uint32_t bRowBase = (uint32_t)(wn * 32 + (lane & 7) + ((lane >> 4) << 3)) * 128u;
    const uint32_t bCol0 = (uint32_t)((lane >> 3) & 1) << 4;

    #pragma unroll
    for (int ks = 0; ks < 4; ks++) {
        const uint32_t ac = (uint32_t)(ks * 32) + aCol0;
        const uint32_t bc = (uint32_t)(ks * 32) + bCol0;
        uint32_t bh[2][4], bl[2][4];
        #pragma unroll
        for (int nh = 0; nh < 2; nh++) {
            const uint32_t bo = bRowBase + (uint32_t)(nh * 16 * 128) + (bc ^ aXor);
            ldsm_x4(sb + T_BHI + bo, bh[nh]);
            ldsm_x4(sb + T_BLO + bo, bl[nh]);
        }
        #pragma unroll
        for (int mt = 0; mt < 4; mt++) {
            const uint32_t ao = aRow + (uint32_t)(mt * 2048) + (ac ^ aXor);
            uint32_t ah[4], al[4];
            ldsm_x4(sb + T_AHI + ao, ah);
            ldsm_x4(sb + T_ALO + ao, al);
            #pragma unroll
            for (int nt = 0; nt < 4; nt++) {
                const uint32_t* bhp = &bh[nt >> 1][(nt & 1) * 2];
                const uint32_t* blp = &bl[nt >> 1][(nt & 1) * 2];
                mma16816(acc[mt][nt], ah, bhp);
                mma16816(acc[mt][nt], ah, blp);
                mma16816(acc[mt][nt], al, bhp);
            }
        }
    }
}

// ---------------------------------------------------------------------------
// Kernel 0: transpose + split V -> g_Vt_hi/lo [b][d][k]
// ---------------------------------------------------------------------------
__global__ __launch_bounds__(256) void vtrans_kernel(const float* __restrict__ V)
{
    __shared__ float tl[32][33];
    const int kt = blockIdx.x * 32, dt = blockIdx.y * 32, b = blockIdx.z;
    const int tx = threadIdx.x, ty = threadIdx.y;

    const float* Vb = V + ((size_t)b * LK_ + kt) * D_ + dt;
    #pragma unroll
    for (int j = 0; j < 4; j++) tl[ty + 8 * j][tx] = Vb[(size_t)(ty + 8 * j) * D_ + tx];
    __syncthreads();

    __nv_bfloat16* Hb = g_Vt_hi + ((size_t)b * D_ + dt) * LK_ + kt;
    __nv_bfloat16* Lb = g_Vt_lo + ((size_t)b * D_ + dt) * LK_ + kt;
    #pragma unroll
    for (int j = 0; j < 4; j++) {
        float f = tl[tx][ty + 8 * j];
        __nv_bfloat16 h, l; split_f(f, h, l);
        Hb[(size_t)(ty + 8 * j) * LK_ + tx] = h;
        Lb[(size_t)(ty + 8 * j) * LK_ + tx] = l;
    }
}

// ---------------------------------------------------------------------------
// Kernel 1: scores. S = (Q . K^T) * INV_T into log_attn region.
// ---------------------------------------------------------------------------
__global__ __launch_bounds__(256) void scores_mma(
    const float* __restrict__ Q, const float* __restrict__ K, float* __restrict__ S)
{
    extern __shared__ __align__(1024) char smem[];
    const uint32_t sb = smem_u32(smem);
    const int t = threadIdx.x, lane = t & 31, wid = t >> 5;
    const int wm = wid & 1, wn = wid >> 1;

    const int b = blockIdx.z, qt = blockIdx.y, kt = blockIdx.x;
    const float* Qb = Q + ((size_t)b * LQ_ + (size_t)qt * 128) * D_;
    const float* Kb = K + ((size_t)b * LK_ + (size_t)kt * 128) * D_;

    float acc[4][4][4];
    #pragma unroll
    for (int i = 0; i < 4; i++)
        #pragma unroll
        for (int j = 0; j < 4; j++)
            #pragma unroll
            for (int g = 0; g < 4; g++) acc[i][j][g] = 0.f;

    const int cg = t & 15;        // 16 col-groups of 4 floats
    const int r0 = t >> 4;        // 16 base rows

    for (int dc = 0; dc < 2; dc++) {
        #pragma unroll
        for (int i = 0; i < 8; i++) {
            const int r = r0 + 16 * i;
            const uint32_t off = (uint32_t)r * 128u + (((uint32_t)cg * 8u) ^ ((uint32_t)(r & 7) << 4));
            float4 q = *(const float4*)(Qb + (size_t)r * D_ + dc * 64 + cg * 4);
            __nv_bfloat16 h0,h1,h2,h3,l0,l1,l2,l3;
            split_f(q.x,h0,l0); split_f(q.y,h1,l1); split_f(q.z,h2,l2); split_f(q.w,h3,l3);
            *(uint2*)(smem + T_AHI + off) = make_uint2(pk_bf2(h0,h1), pk_bf2(h2,h3));
            *(uint2*)(smem + T_ALO + off) = make_uint2(pk_bf2(l0,l1), pk_bf2(l2,l3));
            float4 k4 = *(const float4*)(Kb + (size_t)r * D_ + dc * 64 + cg * 4);
            split_f(k4.x,h0,l0); split_f(k4.y,h1,l1); split_f(k4.z,h2,l2); split_f(k4.w,h3,l3);
            *(uint2*)(smem + T_BHI + off) = make_uint2(pk_bf2(h0,h1), pk_bf2(h2,h3));
            *(uint2*)(smem + T_BLO + off) = make_uint2(pk_bf2(l0,l1), pk_bf2(l2,l3));
        }
        __syncthreads();
        mma_chunk(sb, lane, wm, wn, acc);
        __syncthreads();
    }

    // writeback: thread (g = lane>>2, t4 = lane&3)
    const int g = lane >> 2, t4 = lane & 3;
    #pragma unroll
    for (int mt = 0; mt < 4; mt++) {
        const int m = wm * 64 + mt * 16 + g;
        float* Sr0 = S + ((size_t)(b * LQ_ + qt * 128 + m)) * LK_ + (size_t)kt * 128;
        float* Sr1 = Sr0 + 8 * LK_;
        #pragma unroll
        for (int nt = 0; nt < 4; nt++) {
            const int c = wn * 32 + nt * 8 + 2 * t4;
            *(float2*)(Sr0 + c) = make_float2(acc[mt][nt][0] * INV_T, acc[mt][nt][1] * INV_T);
            *(float2*)(Sr1 + c) = make_float2(acc[mt][nt][2] * INV_T, acc[mt][nt][3] * INV_T);
        }
    }
}

// ---------------------------------------------------------------------------
// Kernel 2: per-row double softmax (mask = int32).
// ---------------------------------------------------------------------------
__global__ __launch_bounds__(256) void softmax_kernel(
    float* __restrict__ S, float* __restrict__ A, const int* __restrict__ M)
{
    __shared__ float2 red[8];
    const int t = threadIdx.x;
    const size_t row = blockIdx.x;

    float4 sv = ((const float4*)(S + row * LK_))[t];
    int4  mv = ((const int4*)(M + row * LK_))[t];

    float mU = fmaxf(fmaxf(sv.x, sv.y), fmaxf(sv.z, sv.w));
    float mM = -3.0e38f;
    if (!mv.x) mM = sv.x;
    if (!mv.y) mM = fmaxf(mM, sv.y);
    if (!mv.z) mM = fmaxf(mM, sv.z);
    if (!mv.w) mM = fmaxf(mM, sv.w);

    #pragma unroll
    for (int o = 16; o > 0; o >>= 1) {
        mU = fmaxf(mU, __shfl_xor_sync(0xffffffffu, mU, o));
        mM = fmaxf(mM, __shfl_xor_sync(0xffffffffu, mM, o));
    }
    if ((t & 31) == 0) red[t >> 5] = make_float2(mU, mM);
    __syncthreads();
    #pragma unroll
    for (int w = 0; w < 8; w++) { mU = fmaxf(mU, red[w].x); mM = fmaxf(mM, red[w].y); }
    __syncthreads();

    float e0 = __expf(sv.x - mU), e1 = __expf(sv.y - mU),
          e2 = __expf(sv.z - mU), e3 = __expf(sv.w - mU);
    float sumU = (e0 + e1) + (e2 + e3);
    float f0 = mv.x ? 0.f : __expf(sv.x - mM);
    float f1 = mv.y ? 0.f : __expf(sv.y - mM);
    float f2 = mv.z ? 0.f : __expf(sv.z - mM);
    float f3 = mv.w ? 0.f : __expf(sv.w - mM);
    float sumM = (f0 + f1) + (f2 + f3);

    #pragma unroll
    for (int o = 16; o > 0; o >>= 1) {
        sumU += __shfl_xor_sync(0xffffffffu, sumU, o);
        sumM += __shfl_xor_sync(0xffffffffu, sumM, o);
    }
    if ((t & 31) == 0) red[t >> 5] = make_float2(sumU, sumM);
    __syncthreads();
    float sU = 0.f, sM = 0.f;
    #pragma unroll
    for (int w = 0; w < 8; w++) { sU += red[w].x; sM += red[w].y; }

    const float lse = mU + __logf(sU);
    const float inv = 1.0f / sM;

    ((float4*)(A + row * LK_))[t] = make_float4(f0 * inv, f1 * inv, f2 * inv, f3 * inv);
    ((float4*)(S + row * LK_))[t] =
        make_float4(sv.x - lse, sv.y - lse, sv.z - lse, sv.w - lse);
}

// ---------------------------------------------------------------------------
// Kernel 3: O = A . V using pre-split Vt [d][k].
// ---------------------------------------------------------------------------
__global__ __launch_bounds__(256) void out_mma(
    const float* __restrict__ A, float* __restrict__ O)
{
    extern __shared__ __align__(1024) char smem[];
    const uint32_t sb = smem_u32(smem);
    const int t = threadIdx.x, lane = t & 31, wid = t >> 5;
    const int wm = wid & 1, wn = wid >> 1;

    const int qt = blockIdx.x, b = blockIdx.y;
    const float* Ab = A + ((size_t)b * LQ_ + (size_t)qt * 128) * LK_;
    const __nv_bfloat16* Vh = g_Vt_hi + (size_t)b * D_ * LK_;
    const __nv_bfloat16* Vl = g_Vt_lo + (size_t)b * D_ * LK_;

    float acc[4][4][4];
    #pragma unroll
    for (int i = 0; i < 4; i++)
        #pragma unroll
        for (int j = 0; j < 4; j++)
            #pragma unroll
            for (int g = 0; g < 4; g++) acc[i][j][g] = 0.f;

    const int cg = t & 15;
    const int r0 = t >> 4;

    for (int kc = 0; kc < 16; kc++) {
        #pragma unroll
        for (int i = 0; i < 8; i++) {
            const int r = r0 + 16 * i;
            const uint32_t off = (uint32_t)r * 128u + (((uint32_t)cg * 8u) ^ ((uint32_t)(r & 7) << 4));
            float4 a4 = *(const float4*)(Ab + (size_t)r * LK_ + kc * 64 + cg * 4);
            __nv_bfloat16 h0,h1,h2,h3,l0,l1,l2,l3;
            split_f(a4.x,h0,l0); split_f(a4.y,h1,l1); split_f(a4.z,h2,l2); split_f(a4.w,h3,l3);
            *(uint2*)(smem + T_AHI + off) = make_uint2(pk_bf2(h0,h1), pk_bf2(h2,h3));
            *(uint2*)(smem + T_ALO + off) = make_uint2(pk_bf2(l0,l1), pk_bf2(l2,l3));
            *(uint2*)(smem + T_BHI + off) =
                *(const uint2*)(Vh + (size_t)r * LK_ + kc * 64 + cg * 4);
            *(uint2*)(smem + T_BLO + off) =
                *(const uint2*)(Vl + (size_t)r * LK_ + kc * 64 + cg * 4);
        }
        __syncthreads();
        mma_chunk(sb, lane, wm, wn, acc);
        __syncthreads();
    }

    const int g = lane >> 2, t4 = lane & 3;
    #pragma unroll
    for (int mt = 0; mt < 4; mt++) {
        const int m = wm * 64 + mt * 16 + g;
        float* Or0 = O + ((size_t)(b * LQ_ + qt * 128 + m)) * D_;
        float* Or1 = Or0 + 8 * D_;
        #pragma unroll
        for (int nt = 0; nt < 4; nt++) {
            const int c = wn * 32 + nt * 8 + 2 * t4;
            *(float2*)(Or0 + c) = make_float2(acc[mt][nt][0], acc[mt][nt][1]);
            *(float2*)(Or1 + c) = make_float2(acc[mt][nt][2], acc[mt][nt][3]);
        }
    }
}

// ---------------------------------------------------------------------------
// Launch. Inputs: q, k, v, attn_mask (int32).
// d_out layout: output | attn | log_attn.  Raw scores staged in log_attn.
// ---------------------------------------------------------------------------
extern "C" void kernel_launch(void* const* d_in, const int* in_sizes, int n_in,
                              void* d_out, int out_size)
{
    (void)in_sizes; (void)n_in; (void)out_size;
    const float* Q = (const float*)d_in[0];
    const float* K = (const float*)d_in[1];
    const float* V = (const float*)d_in[2];
    const int*   M = (const int*)d_in[3];

    float* O   = (float*)d_out;
    float* ATT = O   + (size_t)B_ * LQ_ * D_;
    float* LA  = ATT + (size_t)B_ * LQ_ * LK_;

    cudaFuncSetAttribute(scores_mma, cudaFuncAttributeMaxDynamicSharedMemorySize, SM_TOTAL);
    cudaFuncSetAttribute(out_mma,    cudaFuncAttributeMaxDynamicSharedMemorySize, SM_TOTAL);

    vtrans_kernel<<<dim3(LK_ / 32, D_ / 32, B_), dim3(32, 8)>>>(V);
    scores_mma<<<dim3(LK_ / 128, LQ_ / 128, B_), 256, SM_TOTAL>>>(Q, K, LA);
    softmax_kernel<<<B_ * LQ_, 256>>>(LA, ATT, M);
    out_mma<<<dim3(LQ_ / 128, B_), 256, SM_TOTAL>>>(ATT, O);
}

// round 6
// speedup vs baseline: 2.0135x; 1.4537x over previous
#include <cuda_runtime.h>
#include <cuda_bf16.h>
#include <cstdint>

#define B_   64
#define LQ_  1024
#define LK_  1024
#define D_   128
#define INV_T 0.08838834764831845f   // 1/sqrt(128)

// Scratch (static __device__, allocation-free):
__device__ __nv_bfloat16 g_Qhi[(size_t)B_ * LQ_ * D_];
__device__ __nv_bfloat16 g_Qlo[(size_t)B_ * LQ_ * D_];
__device__ __nv_bfloat16 g_Khi[(size_t)B_ * LK_ * D_];
__device__ __nv_bfloat16 g_Klo[(size_t)B_ * LK_ * D_];
__device__ __nv_bfloat16 g_Vt_hi[(size_t)B_ * D_ * LK_];   // [b][d][k]
__device__ __nv_bfloat16 g_Vt_lo[(size_t)B_ * D_ * LK_];

// ---------------------------------------------------------------------------
// helpers
// ---------------------------------------------------------------------------
__device__ __forceinline__ uint32_t smem_u32(const void* p) {
    uint32_t a;
    asm("{ .reg .u64 t; cvta.to.shared.u64 t, %1; cvt.u32.u64 %0, t; }" : "=r"(a) : "l"(p));
    return a;
}
__device__ __forceinline__ void ldsm_x4(uint32_t addr, uint32_t* r) {
    asm volatile("ldmatrix.sync.aligned.m8n8.x4.shared.b16 {%0,%1,%2,%3}, [%4];"
                 : "=r"(r[0]), "=r"(r[1]), "=r"(r[2]), "=r"(r[3]) : "r"(addr));
}
__device__ __forceinline__ void mma16816(float* d, const uint32_t* a, const uint32_t* b) {
    asm volatile("mma.sync.aligned.m16n8k16.row.col.f32.bf16.bf16.f32 "
                 "{%0,%1,%2,%3}, {%4,%5,%6,%7}, {%8,%9}, {%0,%1,%2,%3};"
                 : "+f"(d[0]), "+f"(d[1]), "+f"(d[2]), "+f"(d[3])
                 : "r"(a[0]), "r"(a[1]), "r"(a[2]), "r"(a[3]), "r"(b[0]), "r"(b[1]));
}
__device__ __forceinline__ void cpasync16(uint32_t dst, const void* src) {
    asm volatile("cp.async.cg.shared.global [%0], [%1], 16;" :: "r"(dst), "l"(src));
}
#define CP_COMMIT() asm volatile("cp.async.commit_group;" ::: "memory")
#define CP_WAIT(n)  asm volatile("cp.async.wait_group %0;" :: "n"(n) : "memory")

__device__ __forceinline__ uint32_t pk_bf2(__nv_bfloat16 a, __nv_bfloat16 b) {
    __nv_bfloat162 t(a, b);
    return *reinterpret_cast<uint32_t*>(&t);
}
__device__ __forceinline__ void split_f(float x, __nv_bfloat16& h, __nv_bfloat16& l) {
    h = __float2bfloat16(x);
    l = __float2bfloat16(x - __bfloat162float(h));
}

// smem: per buffer, 4 tiles of [128 rows][32 bf16 = 64B] = 8KB each; 2 buffers.
#define T_AHI 0
#define T_ALO 8192
#define T_BHI 16384
#define T_BLO 24576
#define BUF_STRIDE 32768
#define SM_TOTAL 65536

// row-swizzled byte offset inside a tile: row r (0..127), 16B group g (0..3)
__device__ __forceinline__ uint32_t swz(uint32_t r, uint32_t g) {
    return r * 64u + ((g ^ ((r >> 1) & 3u)) << 4);
}

// ---------------------------------------------------------------------------
// MMA core over one 32-wide K chunk. Warp grid 2(m) x 4(n); warp tile 64x32.
// ---------------------------------------------------------------------------
__device__ __forceinline__ void mma_chunk32(uint32_t sbuf, int lane, int wm, int wn,
                                            float acc[4][4][4])
{
    const uint32_t arow0 = (uint32_t)(wm * 64 + (lane & 15));
    const uint32_t nrow0 = (uint32_t)(wn * 32 + (lane & 7) + ((lane >> 4) << 3));
    const uint32_t ga = (uint32_t)(lane >> 4);        // 0/1
    const uint32_t gb = (uint32_t)((lane >> 3) & 1);  // 0/1

    #pragma unroll
    for (int ks = 0; ks < 2; ks++) {
        uint32_t bh[2][4], bl[2][4];
        #pragma unroll
        for (int nh = 0; nh < 2; nh++) {
            const uint32_t r = nrow0 + (uint32_t)(nh * 16);
            const uint32_t off = swz(r, (uint32_t)(ks * 2) + gb);
            ldsm_x4(sbuf + T_BHI + off, bh[nh]);
            ldsm_x4(sbuf + T_BLO + off, bl[nh]);
        }
        #pragma unroll
        for (int mt = 0; mt < 4; mt++) {
            const uint32_t r = arow0 + (uint32_t)(mt * 16);
            const uint32_t off = swz(r, (uint32_t)(ks * 2) + ga);
            uint32_t ah[4], al[4];
            ldsm_x4(sbuf + T_AHI + off, ah);
            ldsm_x4(sbuf + T_ALO + off, al);
            #pragma unroll
            for (int nt = 0; nt < 4; nt++) {
                const uint32_t* bhp = &bh[nt >> 1][(nt & 1) * 2];
                const uint32_t* blp = &bl[nt >> 1][(nt & 1) * 2];
                mma16816(acc[mt][nt], ah, bhp);
                mma16816(acc[mt][nt], ah, blp);
                mma16816(acc[mt][nt], al, bhp);
            }
        }
    }
}

// ---------------------------------------------------------------------------
// Prep: elementwise fp32 -> bf16 hi/lo split (for Q and K)
// ---------------------------------------------------------------------------
__global__ __launch_bounds__(256) void split_kernel(
    const float* __restrict__ X, __nv_bfloat16* __restrict__ H, __nv_bfloat16* __restrict__ L)
{
    const size_t i = (size_t)blockIdx.x * 256 + threadIdx.x;
    float4 x = ((const float4*)X)[i];
    __nv_bfloat16 h0,h1,h2,h3,l0,l1,l2,l3;
    split_f(x.x,h0,l0); split_f(x.y,h1,l1); split_f(x.z,h2,l2); split_f(x.w,h3,l3);
    ((uint2*)H)[i] = make_uint2(pk_bf2(h0,h1), pk_bf2(h2,h3));
    ((uint2*)L)[i] = make_uint2(pk_bf2(l0,l1), pk_bf2(l2,l3));
}

// ---------------------------------------------------------------------------
// Prep: transpose + split V -> g_Vt_hi/lo [b][d][k]
// ---------------------------------------------------------------------------
__global__ __launch_bounds__(256) void vtrans_kernel(const float* __restrict__ V)
{
    __shared__ float tl[32][33];
    const int kt = blockIdx.x * 32, dt = blockIdx.y * 32, b = blockIdx.z;
    const int tx = threadIdx.x, ty = threadIdx.y;

    const float* Vb = V + ((size_t)b * LK_ + kt) * D_ + dt;
    #pragma unroll
    for (int j = 0; j < 4; j++) tl[ty + 8 * j][tx] = Vb[(size_t)(ty + 8 * j) * D_ + tx];
    __syncthreads();

    __nv_bfloat16* Hb = g_Vt_hi + ((size_t)b * D_ + dt) * LK_ + kt;
    __nv_bfloat16* Lb = g_Vt_lo + ((size_t)b * D_ + dt) * LK_ + kt;
    #pragma unroll
    for (int j = 0; j < 4; j++) {
        float f = tl[tx][ty + 8 * j];
        __nv_bfloat16 h, l; split_f(f, h, l);
        Hb[(size_t)(ty + 8 * j) * LK_ + tx] = h;
        Lb[(size_t)(ty + 8 * j) * LK_ + tx] = l;
    }
}

// ---------------------------------------------------------------------------
// Kernel 1: scores. S = (Q . K^T) * INV_T into log_attn region.
// Pure cp.async double-buffered pipeline; operands pre-split bf16.
// ---------------------------------------------------------------------------
__device__ __forceinline__ void cp_tile_pair(
    uint32_t sbuf, uint32_t tHI, uint32_t tLO,
    const __nv_bfloat16* __restrict__ Hsrc, const __nv_bfloat16* __restrict__ Lsrc,
    int rowStride, int colOff, int t)
{
    #pragma unroll
    for (int j = 0; j < 2; j++) {
        const uint32_t u = (uint32_t)t + 256u * j;
        const uint32_t row = u >> 2, g = u & 3;
        const uint32_t dst = swz(row, g);
        const size_t so = (size_t)row * rowStride + colOff + g * 8;
        cpasync16(sbuf + tHI + dst, Hsrc + so);
        cpasync16(sbuf + tLO + dst, Lsrc + so);
    }
}

__global__ __launch_bounds__(256, 2) void scores_mma(float* __restrict__ S)
{
    extern __shared__ __align__(1024) char smem[];
    const uint32_t sb = smem_u32(smem);
    const int t = threadIdx.x, lane = t & 31, wid = t >> 5;
    const int wm = wid & 1, wn = wid >> 1;

    const int b = blockIdx.z, qt = blockIdx.y, kt = blockIdx.x;
    const __nv_bfloat16* Qh = g_Qhi + ((size_t)b * LQ_ + (size_t)qt * 128) * D_;
    const __nv_bfloat16* Ql = g_Qlo + ((size_t)b * LQ_ + (size_t)qt * 128) * D_;
    const __nv_bfloat16* Kh = g_Khi + ((size_t)b * LK_ + (size_t)kt * 128) * D_;
    const __nv_bfloat16* Kl = g_Klo + ((size_t)b * LK_ + (size_t)kt * 128) * D_;

    float acc[4][4][4];
    #pragma unroll
    for (int i = 0; i < 4; i++)
        #pragma unroll
        for (int j = 0; j < 4; j++)
            #pragma unroll
            for (int g = 0; g < 4; g++) acc[i][j][g] = 0.f;

    // prologue: chunk 0 -> buf 0
    cp_tile_pair(sb, T_AHI, T_ALO, Qh, Ql, D_, 0, t);
    cp_tile_pair(sb, T_BHI, T_BLO, Kh, Kl, D_, 0, t);
    CP_COMMIT();

    #pragma unroll
    for (int dc = 0; dc < 4; dc++) {
        if (dc + 1 < 4) {
            const uint32_t nb = sb + ((dc + 1) & 1) * BUF_STRIDE;
            cp_tile_pair(nb - sb + sb, T_AHI, T_ALO, Qh, Ql, D_, (dc + 1) * 32, t);
            // (nb) — keep simple:
        }
        if (dc + 1 < 4) {
            const uint32_t nbuf = sb + (uint32_t)(((dc + 1) & 1) * BUF_STRIDE);
            cp_tile_pair(nbuf, T_BHI, T_BLO, Kh, Kl, D_, (dc + 1) * 32, t);
            CP_COMMIT();
            CP_WAIT(1);
        } else {
            CP_WAIT(0);
        }
        __syncthreads();
        mma_chunk32(sb + (uint32_t)((dc & 1) * BUF_STRIDE), lane, wm, wn, acc);
        __syncthreads();
    }

    const int g = lane >> 2, t4 = lane & 3;
    #pragma unroll
    for (int mt = 0; mt < 4; mt++) {
        const int m = wm * 64 + mt * 16 + g;
        float* Sr0 = S + ((size_t)(b * LQ_ + qt * 128 + m)) * LK_ + (size_t)kt * 128;
        float* Sr1 = Sr0 + 8 * LK_;
        #pragma unroll
        for (int nt = 0; nt < 4; nt++) {
            const int c = wn * 32 + nt * 8 + 2 * t4;
            *(float2*)(Sr0 + c) = make_float2(acc[mt][nt][0] * INV_T, acc[mt][nt][1] * INV_T);
            *(float2*)(Sr1 + c) = make_float2(acc[mt][nt][2] * INV_T, acc[mt][nt][3] * INV_T);
        }
    }
}

// ---------------------------------------------------------------------------
// Kernel 2: per-row double softmax (mask = int32).
// ---------------------------------------------------------------------------
__global__ __launch_bounds__(256) void softmax_kernel(
    float* __restrict__ S, float* __restrict__ A, const int* __restrict__ M)
{
    __shared__ float2 red[8];
    const int t = threadIdx.x;
    const size_t row = blockIdx.x;

    float4 sv = ((const float4*)(S + row * LK_))[t];
    int4  mv = ((const int4*)(M + row * LK_))[t];

    float mU = fmaxf(fmaxf(sv.x, sv.y), fmaxf(sv.z, sv.w));
    float mM = -3.0e38f;
    if (!mv.x) mM = sv.x;
    if (!mv.y) mM = fmaxf(mM, sv.y);
    if (!mv.z) mM = fmaxf(mM, sv.z);
    if (!mv.w) mM = fmaxf(mM, sv.w);

    #pragma unroll
    for (int o = 16; o > 0; o >>= 1) {
        mU = fmaxf(mU, __shfl_xor_sync(0xffffffffu, mU, o));
        mM = fmaxf(mM, __shfl_xor_sync(0xffffffffu, mM, o));
    }
    if ((t & 31) == 0) red[t >> 5] = make_float2(mU, mM);
    __syncthreads();
    #pragma unroll
    for (int w = 0; w < 8; w++) { mU = fmaxf(mU, red[w].x); mM = fmaxf(mM, red[w].y); }
    __syncthreads();

    float e0 = __expf(sv.x - mU), e1 = __expf(sv.y - mU),
          e2 = __expf(sv.z - mU), e3 = __expf(sv.w - mU);
    float sumU = (e0 + e1) + (e2 + e3);
    float f0 = mv.x ? 0.f : __expf(sv.x - mM);
    float f1 = mv.y ? 0.f : __expf(sv.y - mM);
    float f2 = mv.z ? 0.f : __expf(sv.z - mM);
    float f3 = mv.w ? 0.f : __expf(sv.w - mM);
    float sumM = (f0 + f1) + (f2 + f3);

    #pragma unroll
    for (int o = 16; o > 0; o >>= 1) {
        sumU += __shfl_xor_sync(0xffffffffu, sumU, o);
        sumM += __shfl_xor_sync(0xffffffffu, sumM, o);
    }
    if ((t & 31) == 0) red[t >> 5] = make_float2(sumU, sumM);
    __syncthreads();
    float sU = 0.f, sM = 0.f;
    #pragma unroll
    for (int w = 0; w < 8; w++) { sU += red[w].x; sM += red[w].y; }

    const float lse = mU + __logf(sU);
    const float inv = 1.0f / sM;

    ((float4*)(A + row * LK_))[t] = make_float4(f0 * inv, f1 * inv, f2 * inv, f3 * inv);
    ((float4*)(S + row * LK_))[t] =
        make_float4(sv.x - lse, sv.y - lse, sv.z - lse, sv.w - lse);
}

// ---------------------------------------------------------------------------
// Kernel 3: O = A . V. A split inline (LDG prefetch), V via cp.async.
// ---------------------------------------------------------------------------
__device__ __forceinline__ void store_A_split(char* smem, uint32_t bufOff,
                                              const float4* a, int t)
{
    #pragma unroll
    for (int i = 0; i < 4; i++) {
        const uint32_t u = (uint32_t)t + 256u * i;
        const uint32_t row = u >> 3, f = u & 7;
        const uint32_t dst = bufOff + swz(row, f >> 1) + (f & 1) * 8;
        __nv_bfloat16 h0,h1,h2,h3,l0,l1,l2,l3;
        split_f(a[i].x,h0,l0); split_f(a[i].y,h1,l1);
        split_f(a[i].z,h2,l2); split_f(a[i].w,h3,l3);
        *(uint2*)(smem + T_AHI + dst) = make_uint2(pk_bf2(h0,h1), pk_bf2(h2,h3));
        *(uint2*)(smem + T_ALO + dst) = make_uint2(pk_bf2(l0,l1), pk_bf2(l2,l3));
    }
}
__device__ __forceinline__ void ldg_A(const float* __restrict__ Ab, int kc, int t, float4* a)
{
    #pragma unroll
    for (int i = 0; i < 4; i++) {
        const uint32_t u = (uint32_t)t + 256u * i;
        const uint32_t row = u >> 3, f = u & 7;
        a[i] = *(const float4*)(Ab + (size_t)row * LK_ + kc * 32 + f * 4);
    }
}

__global__ __launch_bounds__(256, 2) void out_mma(
    const float* __restrict__ A, float* __restrict__ O)
{
    extern __shared__ __align__(1024) char smem[];
    const uint32_t sb = smem_u32(smem);
    const int t = threadIdx.x, lane = t & 31, wid = t >> 5;
    const int wm = wid & 1, wn = wid >> 1;

    const int qt = blockIdx.x, b = blockIdx.y;
    const float* Ab = A + ((size_t)b * LQ_ + (size_t)qt * 128) * LK_;
    const __nv_bfloat16* Vh = g_Vt_hi + (size_t)b * D_ * LK_;
    const __nv_bfloat16* Vl = g_Vt_lo + (size_t)b * D_ * LK_;

    float acc[4][4][4];
    #pragma unroll
    for (int i = 0; i < 4; i++)
        #pragma unroll
        for (int j = 0; j < 4; j++)
            #pragma unroll
            for (int g = 0; g < 4; g++) acc[i][j][g] = 0.f;

    // prologue: chunk 0
    {
        float4 a0[4];
        ldg_A(Ab, 0, t, a0);
        cp_tile_pair(sb, T_BHI, T_BLO, Vh, Vl, LK_, 0, t);
        CP_COMMIT();
        store_A_split(smem, 0, a0, t);
        CP_WAIT(0);
        __syncthreads();
    }

    for (int kc = 0; kc < 32; kc++) {
        float4 an[4];
        const uint32_t nbOff = (uint32_t)(((kc + 1) & 1) * BUF_STRIDE);
        if (kc + 1 < 32) {
            ldg_A(Ab, kc + 1, t, an);                       // LDG in flight
            cp_tile_pair(sb + nbOff, T_BHI, T_BLO, Vh, Vl, LK_, (kc + 1) * 32, t);
            CP_COMMIT();
        }
        mma_chunk32(sb + (uint32_t)((kc & 1) * BUF_STRIDE), lane, wm, wn, acc);
        if (kc + 1 < 32) {
            store_A_split(smem, nbOff, an, t);
            CP_WAIT(0);
        }
        __syncthreads();
    }

    const int g = lane >> 2, t4 = lane & 3;
    #pragma unroll
    for (int mt = 0; mt < 4; mt++) {
        const int m = wm * 64 + mt * 16 + g;
        float* Or0 = O + ((size_t)(b * LQ_ + qt * 128 + m)) * D_;
        float* Or1 = Or0 + 8 * D_;
        #pragma unroll
        for (int nt = 0; nt < 4; nt++) {
            const int c = wn * 32 + nt * 8 + 2 * t4;
            *(float2*)(Or0 + c) = make_float2(acc[mt][nt][0], acc[mt][nt][1]);
            *(float2*)(Or1 + c) = make_float2(acc[mt][nt][2], acc[mt][nt][3]);
        }
    }
}

// ---------------------------------------------------------------------------
// Launch. Inputs: q, k, v, attn_mask (int32).
// d_out layout: output | attn | log_attn.  Raw scores staged in log_attn.
// ---------------------------------------------------------------------------
extern "C" void kernel_launch(void* const* d_in, const int* in_sizes, int n_in,
                              void* d_out, int out_size)
{
    (void)in_sizes; (void)n_in; (void)out_size;
    const float* Q = (const float*)d_in[0];
    const float* K = (const float*)d_in[1];
    const float* V = (const float*)d_in[2];
    const int*   M = (const int*)d_in[3];

    float* O   = (float*)d_out;
    float* ATT = O   + (size_t)B_ * LQ_ * D_;
    float* LA  = ATT + (size_t)B_ * LQ_ * LK_;

    __nv_bfloat16 *qh, *ql, *kh, *kl;
    cudaGetSymbolAddress((void**)&qh, g_Qhi);
    cudaGetSymbolAddress((void**)&ql, g_Qlo);
    cudaGetSymbolAddress((void**)&kh, g_Khi);
    cudaGetSymbolAddress((void**)&kl, g_Klo);

    cudaFuncSetAttribute(scores_mma, cudaFuncAttributeMaxDynamicSharedMemorySize, SM_TOTAL);
    cudaFuncSetAttribute(out_mma,    cudaFuncAttributeMaxDynamicSharedMemorySize, SM_TOTAL);

    const int n4 = B_ * LQ_ * D_ / 4;
    split_kernel<<<n4 / 256, 256>>>(Q, qh, ql);
    split_kernel<<<n4 / 256, 256>>>(K, kh, kl);
    vtrans_kernel<<<dim3(LK_ / 32, D_ / 32, B_), dim3(32, 8)>>>(V);
    scores_mma<<<dim3(LK_ / 128, LQ_ / 128, B_), 256, SM_TOTAL>>>(LA);
    softmax_kernel<<<B_ * LQ_, 256>>>(LA, ATT, M);
    out_mma<<<dim3(LQ_ / 128, B_), 256, SM_TOTAL>>>(ATT, O);
}